// round 14
// baseline (speedup 1.0000x reference)
#include <cuda_runtime.h>

// WidthAP: out[b,0,i,h] = sum_{j=0..4} x[b,0,i+j,h] * attn[b,i+j]
// x: (32,1,2052,768) fp32, attn: (32,2052) fp32, out: (32,1,2048,768) fp32.
//
// R3 shape (512 CTAs, 8-deep front-batched __ldcs LDG.128 bursts protected
// by o[] buffering, 64 regs) with ONE change: stores use DEFAULT cache
// policy (not __stcs). Evict-first reads keep L2 clean so the 126MB L2 can
// buffer dirty output lines and write back in long batched trains ->
// fewer DRAM read/write bus turnarounds.

#define LENGTH   2048
#define WIDTH    5
#define PADDED   (LENGTH + WIDTH - 1)   // 2052
#define BATCH    32
#define HDIM     768
#define H4       (HDIM / 4)             // 192 float4 lanes
#define ITILE    128                    // rows per block
#define NTILES   (LENGTH / ITILE)       // 16
#define UNROLL   8

__device__ __forceinline__ float4 f4_scale(float4 v, float s) {
    return make_float4(v.x * s, v.y * s, v.z * s, v.w * s);
}
__device__ __forceinline__ float4 f4_add(float4 a, float4 b) {
    return make_float4(a.x + b.x, a.y + b.y, a.z + b.z, a.w + b.w);
}

__global__ __launch_bounds__(H4) void widthap_kernel(
    const float4* __restrict__ x,      // (B, PADDED, H4)
    const float*  __restrict__ attn,   // (B, PADDED)
    float4*       __restrict__ out)    // (B, LENGTH, H4)
{
    const int lane = threadIdx.x;          // 0..191, one float4 column
    const int tile = blockIdx.x;           // 0..15
    const int b    = blockIdx.y;           // 0..31
    const int i0   = tile * ITILE;

    __shared__ float w[ITILE + WIDTH - 1]; // 132 weights
    for (int k = lane; k < ITILE + WIDTH - 1; k += blockDim.x)
        w[k] = attn[b * PADDED + i0 + k];
    __syncthreads();

    const float4* xp = x   + ((long)b * PADDED + i0) * H4 + lane;
    float4*       op = out + ((long)b * LENGTH + i0) * H4 + lane;

    // Prime the 5-deep weighted window (first 4 rows).
    float4 v0 = f4_scale(__ldcs(xp + 0 * H4), w[0]);
    float4 v1 = f4_scale(__ldcs(xp + 1 * H4), w[1]);
    float4 v2 = f4_scale(__ldcs(xp + 2 * H4), w[2]);
    float4 v3 = f4_scale(__ldcs(xp + 3 * H4), w[3]);

    for (int i = 0; i < ITILE; i += UNROLL) {
        // Batch of 8 independent streaming loads (front-batched MLP).
        float4 xv[UNROLL];
        #pragma unroll
        for (int u = 0; u < UNROLL; u++)
            xv[u] = __ldcs(xp + (i + 4 + u) * H4);

        // Weighted ring + outputs for 8 rows.
        float4 o[UNROLL];
        #pragma unroll
        for (int u = 0; u < UNROLL; u++) {
            float4 v4 = f4_scale(xv[u], w[i + 4 + u]);
            o[u] = f4_add(f4_add(f4_add(v0, v1), f4_add(v2, v3)), v4);
            v0 = v1; v1 = v2; v2 = v3; v3 = v4;
        }

        // Batch of 8 stores, default cache policy (L2 write-buffered).
        #pragma unroll
        for (int u = 0; u < UNROLL; u++)
            op[(i + u) * H4] = o[u];
    }
}

extern "C" void kernel_launch(void* const* d_in, const int* in_sizes, int n_in,
                              void* d_out, int out_size)
{
    const float4* x    = (const float4*)d_in[0];
    const float*  attn = (const float*)d_in[1];
    float4*       out  = (float4*)d_out;

    dim3 grid(NTILES, BATCH);
    widthap_kernel<<<grid, H4>>>(x, attn, out);
}

// round 15
// speedup vs baseline: 1.0343x; 1.0343x over previous
#include <cuda_runtime.h>

// WidthAP: out[b,0,i,h] = sum_{j=0..4} x[b,0,i+j,h] * attn[b,i+j]
// x: (32,1,2052,768) fp32, attn: (32,2052) fp32, out: (32,1,2048,768) fp32.
//
// Converged configuration (best of 14 rounds): 512 CTAs (ITILE=128),
// 8-deep front-batched __ldcs LDG.128 bursts protected by o[] buffering
// (64 regs — deeper/shallower or capped variants all regress), __stcs
// stores (beat default policy), tiny static smem (low graph-replay cost).
// DRAM-bound at the ~73% mixed read/write stream ceiling (5.8 TB/s);
// traffic is within 3% of the theoretical minimum.

#define LENGTH   2048
#define WIDTH    5
#define PADDED   (LENGTH + WIDTH - 1)   // 2052
#define BATCH    32
#define HDIM     768
#define H4       (HDIM / 4)             // 192 float4 lanes
#define ITILE    128                    // rows per block
#define NTILES   (LENGTH / ITILE)       // 16
#define UNROLL   8

__device__ __forceinline__ float4 f4_scale(float4 v, float s) {
    return make_float4(v.x * s, v.y * s, v.z * s, v.w * s);
}
__device__ __forceinline__ float4 f4_add(float4 a, float4 b) {
    return make_float4(a.x + b.x, a.y + b.y, a.z + b.z, a.w + b.w);
}

__global__ __launch_bounds__(H4) void widthap_kernel(
    const float4* __restrict__ x,      // (B, PADDED, H4)
    const float*  __restrict__ attn,   // (B, PADDED)
    float4*       __restrict__ out)    // (B, LENGTH, H4)
{
    const int lane = threadIdx.x;          // 0..191, one float4 column
    const int tile = blockIdx.x;           // 0..15
    const int b    = blockIdx.y;           // 0..31
    const int i0   = tile * ITILE;

    __shared__ float w[ITILE + WIDTH - 1]; // 132 weights
    for (int k = lane; k < ITILE + WIDTH - 1; k += blockDim.x)
        w[k] = attn[b * PADDED + i0 + k];
    __syncthreads();

    const float4* xp = x   + ((long)b * PADDED + i0) * H4 + lane;
    float4*       op = out + ((long)b * LENGTH + i0) * H4 + lane;

    // Prime the 5-deep weighted window (first 4 rows).
    float4 v0 = f4_scale(__ldcs(xp + 0 * H4), w[0]);
    float4 v1 = f4_scale(__ldcs(xp + 1 * H4), w[1]);
    float4 v2 = f4_scale(__ldcs(xp + 2 * H4), w[2]);
    float4 v3 = f4_scale(__ldcs(xp + 3 * H4), w[3]);

    for (int i = 0; i < ITILE; i += UNROLL) {
        // Batch of 8 independent streaming loads (front-batched MLP).
        float4 xv[UNROLL];
        #pragma unroll
        for (int u = 0; u < UNROLL; u++)
            xv[u] = __ldcs(xp + (i + 4 + u) * H4);

        // Weighted ring + outputs for 8 rows.
        float4 o[UNROLL];
        #pragma unroll
        for (int u = 0; u < UNROLL; u++) {
            float4 v4 = f4_scale(xv[u], w[i + 4 + u]);
            o[u] = f4_add(f4_add(f4_add(v0, v1), f4_add(v2, v3)), v4);
            v0 = v1; v1 = v2; v2 = v3; v3 = v4;
        }

        // Batch of 8 streaming stores.
        #pragma unroll
        for (int u = 0; u < UNROLL; u++)
            __stcs(op + (i + u) * H4, o[u]);
    }
}

extern "C" void kernel_launch(void* const* d_in, const int* in_sizes, int n_in,
                              void* d_out, int out_size)
{
    const float4* x    = (const float4*)d_in[0];
    const float*  attn = (const float*)d_in[1];
    float4*       out  = (float4*)d_out;

    dim3 grid(NTILES, BATCH);
    widthap_kernel<<<grid, H4>>>(x, attn, out);
}